// round 2
// baseline (speedup 1.0000x reference)
#include <cuda_runtime.h>
#include <cstddef>

#define NEG (-1e20f)

constexpr int NA = 512;    // rows i = 1..NA
constexpr int NB = 1024;   // cols j = 1..NB
constexpr int NT = 1024;   // threads = one per column
constexpr int NWIN = 48;   // 48 windows * 32 steps = 1536 steps (s = 2..1537)

// shared memory layout (floats):
//   wband   [32][1024]  : W values for the current 32-step diagonal window
//   outband [512][32]   : computed mu values awaiting coalesced flush
//   bnd     [2][33]     : cross-warp boundary (double-buffered by step parity)
constexpr int WBAND_F   = 32 * NB;
constexpr int OUTBAND_F = NA * 32;
constexpr int BND_F     = 2 * 33;
constexpr int SMEM_F    = WBAND_F + OUTBAND_F + BND_F;

__device__ __forceinline__ float lse3(float a, float b, float c) {
    float m = fmaxf(a, fmaxf(b, c));
    float s = __expf(a - m) + __expf(b - m) + __expf(c - m);
    return m + __logf(s);
}

__global__ void __launch_bounds__(NT, 1)
dtw_wavefront_kernel(const float* __restrict__ W, float* __restrict__ out) {
    extern __shared__ float smem[];
    float* wband   = smem;                  // [slot][t], slot = s & 31
    float* outband = smem + WBAND_F;        // [r][ (j-1) & 31 ], r = i-1
    float* bnd     = smem + WBAND_F + OUTBAND_F;  // [parity][warp]

    const int b    = blockIdx.x;
    const int t    = threadIdx.x;           // column j = t + 1
    const int lane = t & 31;
    const int wid  = t >> 5;

    const float* Wb = W + (size_t)b * NA * NB;
    float* Ob = out + (size_t)b * (NA + 1) * (NB + 1);

    // --- edge outputs: mu[0, :] and mu[:, 0] ---
    Ob[t] = (t == 0) ? 0.0f : NEG;                        // row 0, cols 0..1023
    if (t == 0) Ob[NB] = NEG;                             // row 0, col 1024 (the R1 bug)
    if (t < NA)  Ob[(size_t)(t + 1) * (NB + 1)] = NEG;    // col 0

    if (t < BND_F) bnd[t] = NEG;
    __syncthreads();

    float v1    = NEG;   // this column's most recently computed mu (starts as mu[0, j] = NEG)
    float lprev = NEG;   // left neighbor's v1 from the PREVIOUS step (= upper-left)

    for (int k = 0; k < NWIN; ++k) {
        const int S = 2 + 32 * k;   // first step of this window; S mod 32 == 2

        // ---- fill wband for steps [S, S+32): coalesced per-row segments ----
        // warp `wid` handles W rows r = wid + 32*m; for row r the window needs
        // cols t = S-2-r + lane (32 consecutive). slot = (s & 31) = (lane+2) & 31.
        {
            float vals[16];
            int   tts[16];
            #pragma unroll
            for (int m = 0; m < 16; ++m) {
                int r  = wid + (m << 5);
                int tt = S - 2 - r + lane;
                bool ok = (tt >= 0) && (tt < NB);
                tts[m] = ok ? tt : -1;
                vals[m] = ok ? Wb[r * NB + tt] : 0.0f;
            }
            const int slot = (lane + 2) & 31;
            #pragma unroll
            for (int m = 0; m < 16; ++m) {
                if (tts[m] >= 0) wband[slot * NB + tts[m]] = vals[m];
            }
        }
        __syncthreads();

        // ---- 32 wavefront steps ----
        for (int q = 0; q < 32; ++q) {
            const int s = S + q;
            const int i = s - t - 1;    // row this thread computes at step s

            float lv = __shfl_up_sync(0xFFFFFFFFu, v1, 1);
            if (lane == 0) lv = bnd[(s & 1) * 33 + wid];
            float ul = lprev;
            if (t == 0) { lv = NEG; ul = (i == 1) ? 0.0f : NEG; }

            if (i >= 1 && i <= NA) {
                float w    = wband[(s & 31) * NB + t];
                float mval = lse3(v1, lv, ul) + w;
                outband[(i - 1) * 32 + (t & 31)] = mval;
                v1 = mval;
            }
            lprev = lv;
            if (lane == 31) bnd[((s & 1) ^ 1) * 33 + (wid + 1)] = v1;
            __syncthreads();
        }

        // ---- flush outband: cells computed in steps [S, S+32) ----
        // row i got cols j = S - i + lane (32 consecutive, clipped)
        #pragma unroll
        for (int m = 0; m < 16; ++m) {
            int r = wid + (m << 5);
            int i = r + 1;
            int j = S - i + lane;
            if (j >= 1 && j <= NB) {
                Ob[(size_t)i * (NB + 1) + j] = outband[r * 32 + ((j - 1) & 31)];
            }
        }
        __syncthreads();
    }
}

extern "C" void kernel_launch(void* const* d_in, const int* in_sizes, int n_in,
                              void* d_out, int out_size) {
    const float* W = (const float*)d_in[0];
    float* out = (float*)d_out;
    const size_t smem_bytes = SMEM_F * sizeof(float);
    cudaFuncSetAttribute(dtw_wavefront_kernel,
                         cudaFuncAttributeMaxDynamicSharedMemorySize,
                         (int)smem_bytes);
    dtw_wavefront_kernel<<<32, NT, smem_bytes>>>(W, out);
}